// round 14
// baseline (speedup 1.0000x reference)
#include <cuda_runtime.h>
#include <math.h>

#define PTS 4096      // B*N = 8*512

// ---------------- packed activation / weight scratch -------------------------
__device__ unsigned g_peh[PTS * 128],  g_pel[PTS * 128];
__device__ unsigned g_feath[PTS * 8],  g_featl[PTS * 8];
__device__ float    g_spatial[PTS * 256];
__device__ unsigned g_spath[PTS * 128], g_spatl[PTS * 128];
__device__ unsigned g_h1h[PTS * 64],   g_h1l[PTS * 64];
__device__ unsigned g_freqh[PTS * 128], g_freql[PTS * 128];
__device__ unsigned g_qkh[2u * PTS * 128], g_qkl[2u * PTS * 128];
__device__ float    g_v[PTS * 256];
__device__ unsigned g_oh[PTS * 128],   g_ol[PTS * 128];
__device__ float    g_x[PTS * 256];
__device__ unsigned g_xh[PTS * 128],   g_xl[PTS * 128];
__device__ unsigned g_ffhh[PTS * 256], g_ffhl[PTS * 256];
__device__ unsigned g_x2h[PTS * 128],  g_x2l[PTS * 128];
__device__ unsigned g_wh[345088],      g_wl[345088];

// weight segment offsets (in pairs)
#define OFF_PE   0
#define OFF_FE1  32768
#define OFF_FE2  33792
#define OFF_IN   50176
#define OFF_AO   148480
#define OFF_F1   181248
#define OFF_F2   246784
#define OFF_OP   312320
#define TOT_PAIRS 345088

__device__ __forceinline__ float gelu_f(float x) {
    return 0.5f * x * (1.0f + erff(x * 0.7071067811865475f));
}

// tf32 helpers (attention PV path) -------------------------------------------
__device__ __forceinline__ unsigned tf32_rna(float x) {
    unsigned r;
    asm("cvt.rna.tf32.f32 %0, %1;" : "=r"(r) : "f"(x));
    return r;
}
__device__ __forceinline__ void mma8(float* c, unsigned a0, unsigned a1,
                                     unsigned a2, unsigned a3,
                                     unsigned b0, unsigned b1) {
    asm("mma.sync.aligned.m16n8k8.row.col.f32.tf32.tf32.f32 "
        "{%0,%1,%2,%3},{%4,%5,%6,%7},{%8,%9},{%0,%1,%2,%3};"
        : "+f"(c[0]), "+f"(c[1]), "+f"(c[2]), "+f"(c[3])
        : "r"(a0), "r"(a1), "r"(a2), "r"(a3), "r"(b0), "r"(b1));
}
__device__ __forceinline__ void split_tf32(float x, unsigned& hi, unsigned& lo) {
    hi = tf32_rna(x);
    lo = __float_as_uint(x - __uint_as_float(hi));
}

// bf16x2 helpers --------------------------------------------------------------
__device__ __forceinline__ void packsplit(float x0, float x1,
                                          unsigned& h, unsigned& l) {
    unsigned hh;
    asm("cvt.rn.bf16x2.f32 %0, %1, %2;" : "=r"(hh) : "f"(x1), "f"(x0));
    float r0 = x0 - __uint_as_float(hh << 16);
    float r1 = x1 - __uint_as_float(hh & 0xffff0000u);
    asm("cvt.rn.bf16x2.f32 %0, %1, %2;" : "=r"(l) : "f"(r1), "f"(r0));
    h = hh;
}
__device__ __forceinline__ void mma16(float* c,
                                      unsigned a0, unsigned a1, unsigned a2, unsigned a3,
                                      unsigned b0, unsigned b1) {
    asm("mma.sync.aligned.m16n8k16.row.col.f32.bf16.bf16.f32 "
        "{%0,%1,%2,%3},{%4,%5,%6,%7},{%8,%9},{%0,%1,%2,%3};"
        : "+f"(c[0]), "+f"(c[1]), "+f"(c[2]), "+f"(c[3])
        : "r"(a0), "r"(a1), "r"(a2), "r"(a3), "r"(b0), "r"(b1));
}
__device__ __forceinline__ void mma_x3p(float* c,
                                        unsigned a0h, unsigned a1h, unsigned a2h, unsigned a3h,
                                        unsigned a0l, unsigned a1l, unsigned a2l, unsigned a3l,
                                        unsigned b0h, unsigned b1h,
                                        unsigned b0l, unsigned b1l) {
    mma16(c, a0l, a1l, a2l, a3l, b0h, b1h);
    mma16(c, a0h, a1h, a2h, a3h, b0l, b1l);
    mma16(c, a0h, a1h, a2h, a3h, b0h, b1h);
}

// ---------------- prep: FFT feat (0..4095) | PE (4096..6143) | pack W -------
__global__ void __launch_bounds__(256) prep_kernel(
    const float* __restrict__ image, const float* __restrict__ coords,
    const float* __restrict__ fbi,
    unsigned* __restrict__ feath, unsigned* __restrict__ featl,
    unsigned* __restrict__ peh, unsigned* __restrict__ pel,
    const float* __restrict__ pe_w, const float* __restrict__ fe1_w,
    const float* __restrict__ fe2_w, const float* __restrict__ in_w,
    const float* __restrict__ ao_w, const float* __restrict__ f1_w,
    const float* __restrict__ f2_w, const float* __restrict__ op_w,
    unsigned* __restrict__ wh, unsigned* __restrict__ wl)
{
    int tid = threadIdx.x;
    if (blockIdx.x >= 6144) {
        int p = (blockIdx.x - 6144) * 256 + tid;
        if (p < TOT_PAIRS) {
            const float* src;
            if      (p < OFF_FE1) src = pe_w  + (size_t)(p - OFF_PE) * 2;
            else if (p < OFF_FE2) src = fe1_w + (size_t)(p - OFF_FE1) * 2;
            else if (p < OFF_IN)  src = fe2_w + (size_t)(p - OFF_FE2) * 2;
            else if (p < OFF_AO)  src = in_w  + (size_t)(p - OFF_IN) * 2;
            else if (p < OFF_F1)  src = ao_w  + (size_t)(p - OFF_AO) * 2;
            else if (p < OFF_F2)  src = f1_w  + (size_t)(p - OFF_F1) * 2;
            else if (p < OFF_OP)  src = f2_w  + (size_t)(p - OFF_F2) * 2;
            else                  src = op_w  + (size_t)(p - OFF_OP) * 2;
            float2 v = *(const float2*)src;
            packsplit(v.x, v.y, wh[p], wl[p]);
        }
        return;
    }
    if (blockIdx.x >= 4096) {
        int idx = blockIdx.x - 4096;
        int pt = idx * 2 + (tid >> 7);
        int p = tid & 127;
        int region = p >> 5;
        int comp = p >> 6;
        int i0 = (2 * p) & 63;
        float c = coords[pt * 2 + comp] * (1.0f / 1024.0f);
        float a0 = c * 6.283185307179586f * exp2f(-(float)i0 * 0.4152410118609203f);
        float a1 = c * 6.283185307179586f * exp2f(-(float)(i0 + 1) * 0.4152410118609203f);
        float s0, c0, s1, c1;
        sincosf(a0, &s0, &c0);
        sincosf(a1, &s1, &c1);
        float v0 = (region & 1) ? c0 : s0;
        float v1 = (region & 1) ? c1 : s1;
        packsplit(v0, v1, peh[(size_t)pt * 128 + p], pel[(size_t)pt * 128 + p]);
        return;
    }

    int pt = blockIdx.x;
    int b = pt >> 9;

    __shared__ float patch[16][16];
    __shared__ float Rre[16][9], Rim[16][9];
    __shared__ float twc[16], tws[16];
    __shared__ float bmag[8], bang[8];
    __shared__ int bcnt[8];
    __shared__ float smf[8];
    __shared__ float fv[16];
    __shared__ int spx, spy;

    if (tid == 0) {
        float cx = coords[pt * 2];
        float cy = coords[pt * 2 + 1];
        int px = (int)cx; px = min(max(px, 8), 1015);
        int py = (int)cy; py = min(max(py, 8), 1015);
        spx = px; spy = py;
        float mx = -1e30f;
        for (int i = 0; i < 8; i++) mx = fmaxf(mx, fbi[i]);
        float s = 0.0f;
        for (int i = 0; i < 8; i++) { float e = expf(fbi[i] - mx); smf[i] = e; s += e; }
        float inv = 1.0f / s;
        for (int i = 0; i < 8; i++) smf[i] *= inv;
    }
    if (tid < 16) {
        twc[tid] = cospif((float)tid / 8.0f);
        tws[tid] = sinpif(-(float)tid / 8.0f);
    }
    if (tid < 8) { bmag[tid] = 0.0f; bang[tid] = 0.0f; bcnt[tid] = 0; }
    __syncthreads();

    int y = tid >> 4, x = tid & 15;
    int yy = spy - 8 + y, xx = spx - 8 + x;
    const float* imb = image + (size_t)b * 3u * 1024u * 1024u;
    size_t off = (size_t)yy * 1024 + xx;
    float gsum = imb[off] + imb[1048576u + off] + imb[2097152u + off];
    patch[y][x] = gsum * (1.0f / 3.0f);
    __syncthreads();

    if (tid < 144) {
        int ry = tid / 9, kx = tid % 9;
        float re = 0.0f, im = 0.0f;
#pragma unroll
        for (int j = 0; j < 16; j++) {
            float pv = patch[ry][j];
            int t = (kx * j) & 15;
            re += pv * twc[t];
            im += pv * tws[t];
        }
        Rre[ry][kx] = re;
        Rim[ry][kx] = im;
    }
    __syncthreads();

    if (tid < 144) {
        int ky = tid / 9, kx = tid % 9;
        float re = 0.0f, im = 0.0f;
#pragma unroll
        for (int j = 0; j < 16; j++) {
            int t = (ky * j) & 15;
            float c = twc[t], s = tws[t];
            float ar = Rre[j][kx], ai = Rim[j][kx];
            re += ar * c - ai * s;
            im += ar * s + ai * c;
        }
        re *= 0.0625f;
        im *= 0.0625f;
        float mag = sqrtf(re * re + im * im);
        float ang = atan2f(im, re);

        double fy = (ky < 8) ? (double)ky / 16.0 : ((double)ky - 16.0) / 16.0;
        double fx = (double)kx / 16.0;
        double r = sqrt(fx * fx + fy * fy);
        double maxr = 0.7071067811865476 + 1e-6;
        double step = maxr / 8.0;
        int bi = 0;
#pragma unroll
        for (int k = 1; k < 9; k++) if (r >= (double)k * step) bi = k;
        if (bi > 7) bi = 7;
        atomicAdd(&bmag[bi], mag);
        atomicAdd(&bang[bi], ang);
        atomicAdd(&bcnt[bi], 1);
    }
    __syncthreads();

    if (tid < 8) {
        float c = (float)max(bcnt[tid], 1);
        fv[tid]     = bmag[tid] / c * smf[tid];
        fv[8 + tid] = bang[tid] / c;
    }
    __syncthreads();
    if (tid < 8) {
        packsplit(fv[2 * tid], fv[2 * tid + 1],
                  feath[(size_t)pt * 8 + tid], featl[(size_t)pt * 8 + tid]);
    }
}

// ---------------- packed bf16x3 GEMM: C = A @ B^T + bias --------------------
// 64x64 tile, 128 threads (2x2 warps), double-buffered, [row][8] smem.
template <int EP>
__global__ void __launch_bounds__(128) gemm_p(
    const unsigned* __restrict__ Ah, const unsigned* __restrict__ Al,
    const unsigned* __restrict__ Bh, const unsigned* __restrict__ Bl,
    const float* __restrict__ bias,
    float* __restrict__ Cf, unsigned* __restrict__ Ch, unsigned* __restrict__ Cl,
    int K2, int ldcF, int ldp,
    const int* __restrict__ labels, const float* __restrict__ temb,
    const unsigned* __restrict__ A2h, const unsigned* __restrict__ A2l)
{
    __shared__ unsigned Ahs[2][64][8], Als[2][64][8];
    __shared__ unsigned Bhs[2][64][8], Bls[2][64][8];

    int z = 0;
    if (EP == 4) {
        z = blockIdx.z;
        if (z > 0) { Ah = A2h; Al = A2l; }
        Bh += (size_t)z * 32768;
        Bl += (size_t)z * 32768;
        bias += z << 8;
    }

    const int tid = threadIdx.x;
    const int m0 = blockIdx.y << 6, n0 = blockIdx.x << 6;
    const int srow = tid >> 1, sseg = (tid & 1) << 2;

    const unsigned* Aph = Ah + (size_t)(m0 + srow) * K2 + sseg;
    const unsigned* Apl = Al + (size_t)(m0 + srow) * K2 + sseg;
    const unsigned* Bph = Bh + (size_t)(n0 + srow) * K2 + sseg;
    const unsigned* Bpl = Bl + (size_t)(n0 + srow) * K2 + sseg;

    const int lane = tid & 31, wid = tid >> 5;
    const int g = lane >> 2, t4 = lane & 3;
    const int wm = (wid >> 1) << 5, wn = (wid & 1) << 5;

    float acc[2][4][4] = {};

    *(uint4*)&Ahs[0][srow][sseg] = *(const uint4*)Aph;
    *(uint4*)&Als[0][srow][sseg] = *(const uint4*)Apl;
    *(uint4*)&Bhs[0][srow][sseg] = *(const uint4*)Bph;
    *(uint4*)&Bls[0][srow][sseg] = *(const uint4*)Bpl;
    __syncthreads();

    int buf = 0;
    for (int k20 = 0; k20 < K2; k20 += 8) {
        const bool notlast = (k20 + 8 < K2);
        uint4 pah, pal, pbh, pbl;
        if (notlast) {
            pah = *(const uint4*)(Aph + k20 + 8);
            pal = *(const uint4*)(Apl + k20 + 8);
            pbh = *(const uint4*)(Bph + k20 + 8);
            pbl = *(const uint4*)(Bpl + k20 + 8);
        }

        unsigned bh0[4], bh1[4], bl0[4], bl1[4];
#pragma unroll
        for (int ni = 0; ni < 4; ni++) {
            int c = wn + ni * 8 + g;
            bh0[ni] = Bhs[buf][c][t4];     bl0[ni] = Bls[buf][c][t4];
            bh1[ni] = Bhs[buf][c][t4 + 4]; bl1[ni] = Bls[buf][c][t4 + 4];
        }
#pragma unroll
        for (int mi = 0; mi < 2; mi++) {
            int r0 = wm + mi * 16 + g, r1 = r0 + 8;
            unsigned a0h = Ahs[buf][r0][t4],     a0l = Als[buf][r0][t4];
            unsigned a1h = Ahs[buf][r1][t4],     a1l = Als[buf][r1][t4];
            unsigned a2h = Ahs[buf][r0][t4 + 4], a2l = Als[buf][r0][t4 + 4];
            unsigned a3h = Ahs[buf][r1][t4 + 4], a3l = Als[buf][r1][t4 + 4];
#pragma unroll
            for (int ni = 0; ni < 4; ni++)
                mma_x3p(acc[mi][ni], a0h, a1h, a2h, a3h, a0l, a1l, a2l, a3l,
                        bh0[ni], bh1[ni], bl0[ni], bl1[ni]);
        }

        if (notlast) {
            int nb = buf ^ 1;
            *(uint4*)&Ahs[nb][srow][sseg] = pah;
            *(uint4*)&Als[nb][srow][sseg] = pal;
            *(uint4*)&Bhs[nb][srow][sseg] = pbh;
            *(uint4*)&Bls[nb][srow][sseg] = pbl;
            __syncthreads();
            buf = nb;
        }
    }

#pragma unroll
    for (int mi = 0; mi < 2; mi++) {
        int r0 = m0 + wm + mi * 16 + g;
        int r1 = r0 + 8;
        const float* t0 = nullptr;
        const float* t1 = nullptr;
        if (EP == 2) {
            t0 = temb + (size_t)labels[r0] * 256;
            t1 = temb + (size_t)labels[r1] * 256;
        }
#pragma unroll
        for (int ni = 0; ni < 4; ni++) {
            int c0 = n0 + wn + ni * 8 + (t4 << 1);
            float v00 = acc[mi][ni][0], v01 = acc[mi][ni][1];
            float v10 = acc[mi][ni][2], v11 = acc[mi][ni][3];
            float bx = bias[c0], by = bias[c0 + 1];
            v00 += bx; v01 += by; v10 += bx; v11 += by;
            if (EP == 1) {
                v00 = gelu_f(v00); v01 = gelu_f(v01);
                v10 = gelu_f(v10); v11 = gelu_f(v11);
            }
            if (EP == 2) {
                v00 += t0[c0]; v01 += t0[c0 + 1];
                v10 += t1[c0]; v11 += t1[c0 + 1];
            }
            if (EP == 4) {
                if (z < 2) {
                    unsigned h0, l0, h1, l1;
                    packsplit(v00, v01, h0, l0);
                    packsplit(v10, v11, h1, l1);
                    size_t i0 = ((size_t)z * PTS + r0) * 128 + (c0 >> 1);
                    size_t i1 = ((size_t)z * PTS + r1) * 128 + (c0 >> 1);
                    Ch[i0] = h0; Cl[i0] = l0;
                    Ch[i1] = h1; Cl[i1] = l1;
                } else {
                    *(float2*)(Cf + (size_t)r0 * ldcF + c0) = make_float2(v00, v01);
                    *(float2*)(Cf + (size_t)r1 * ldcF + c0) = make_float2(v10, v11);
                }
            } else {
                if (Cf) {
                    *(float2*)(Cf + (size_t)r0 * ldcF + c0) = make_float2(v00, v01);
                    *(float2*)(Cf + (size_t)r1 * ldcF + c0) = make_float2(v10, v11);
                }
                if (Ch) {
                    unsigned h0, l0, h1, l1;
                    packsplit(v00, v01, h0, l0);
                    packsplit(v10, v11, h1, l1);
                    size_t i0 = (size_t)r0 * ldp + (c0 >> 1);
                    size_t i1 = (size_t)r1 * ldp + (c0 >> 1);
                    Ch[i0] = h0; Cl[i0] = l0;
                    Ch[i1] = h1; Cl[i1] = l1;
                }
            }
        }
    }
}

// ---------------- packed GEMM + fused LayerNorm: 32 x W tile, 8 warps -------
// Each warp owns 32 rows x W/8 cols. grid = 128, 256 threads.
template <int W, bool RES, bool GELU_AFTER>
__global__ void __launch_bounds__(256) gemm_pln(
    const unsigned* __restrict__ Ah, const unsigned* __restrict__ Al,
    const unsigned* __restrict__ Bh, const unsigned* __restrict__ Bl,
    const float* __restrict__ bias, const float* __restrict__ res,
    const float* __restrict__ gam, const float* __restrict__ bet,
    float* __restrict__ Cf, unsigned* __restrict__ Ch, unsigned* __restrict__ Cl,
    int K2)
{
    constexpr int NI = W / 64;           // n8-tiles per warp (8 warps)
    __shared__ unsigned Ahs[2][32][8], Als[2][32][8];
    __shared__ unsigned Bhs[2][W][8],  Bls[2][W][8];
    __shared__ float rsum[32][8], rsq[32][8];
    __shared__ float smean[32], sistd[32];

    const int tid = threadIdx.x;
    const int m0 = blockIdx.x << 5;

    // A staging by tid<128: 32 rows x 8 k2, uint2/thread
    const int arow = (tid & 127) >> 2, aseg = (tid & 3) << 1;
    const unsigned* Aph = Ah + (size_t)(m0 + arow) * K2 + aseg;
    const unsigned* Apl = Al + (size_t)(m0 + arow) * K2 + aseg;
    // B staging: row tid (tid < W), full 8-word row as 2 uint4
    const unsigned* Bph = Bh + (size_t)tid * K2;
    const unsigned* Bpl = Bl + (size_t)tid * K2;

    const int lane = tid & 31, wid = tid >> 5;
    const int g = lane >> 2, t4 = lane & 3;
    const int wn = wid * (W / 8);

    float acc[2][NI][4] = {};

    {
        if (tid < 128) {
            *(uint2*)&Ahs[0][arow][aseg] = *(const uint2*)Aph;
            *(uint2*)&Als[0][arow][aseg] = *(const uint2*)Apl;
        }
        if (tid < W) {
            *(uint4*)&Bhs[0][tid][0] = *(const uint4*)Bph;
            *(uint4*)&Bhs[0][tid][4] = *(const uint4*)(Bph + 4);
            *(uint4*)&Bls[0][tid][0] = *(const uint4*)Bpl;
            *(uint4*)&Bls[0][tid][4] = *(const uint4*)(Bpl + 4);
        }
    }
    __syncthreads();

    int buf = 0;
    for (int k20 = 0; k20 < K2; k20 += 8) {
        const bool notlast = (k20 + 8 < K2);
        uint2 pah, pal;
        uint4 pbh0, pbh1, pbl0, pbl1;
        if (notlast) {
            if (tid < 128) {
                pah = *(const uint2*)(Aph + k20 + 8);
                pal = *(const uint2*)(Apl + k20 + 8);
            }
            if (tid < W) {
                pbh0 = *(const uint4*)(Bph + k20 + 8);
                pbh1 = *(const uint4*)(Bph + k20 + 12);
                pbl0 = *(const uint4*)(Bpl + k20 + 8);
                pbl1 = *(const uint4*)(Bpl + k20 + 12);
            }
        }

        unsigned a0h[2], a1h[2], a2h[2], a3h[2], a0l[2], a1l[2], a2l[2], a3l[2];
#pragma unroll
        for (int mi = 0; mi < 2; mi++) {
            int r0 = mi * 16 + g, r1 = r0 + 8;
            a0h[mi] = Ahs[buf][r0][t4];     a0l[mi] = Als[buf][r0][t4];
            a1h[mi] = Ahs[buf][r1][t4];     a1l[mi] = Als[buf][r1][t4];
            a2h[mi] = Ahs[buf][r0][t4 + 4]; a2l[mi] = Als[buf][r0][t4 + 4];
            a3h[mi] = Ahs[buf][r1][t4 + 4]; a3l[mi] = Als[buf][r1][t4 + 4];
        }
#pragma unroll
        for (int ni = 0; ni < NI; ni++) {
            int c = wn + ni * 8 + g;
            unsigned bh0 = Bhs[buf][c][t4],     bl0 = Bls[buf][c][t4];
            unsigned bh1 = Bhs[buf][c][t4 + 4], bl1 = Bls[buf][c][t4 + 4];
#pragma unroll
            for (int mi = 0; mi < 2; mi++)
                mma_x3p(acc[mi][ni], a0h[mi], a1h[mi], a2h[mi], a3h[mi],
                        a0l[mi], a1l[mi], a2l[mi], a3l[mi], bh0, bh1, bl0, bl1);
        }

        if (notlast) {
            int nb = buf ^ 1;
            if (tid < 128) {
                *(uint2*)&Ahs[nb][arow][aseg] = pah;
                *(uint2*)&Als[nb][arow][aseg] = pal;
            }
            if (tid < W) {
                *(uint4*)&Bhs[nb][tid][0] = pbh0;
                *(uint4*)&Bhs[nb][tid][4] = pbh1;
                *(uint4*)&Bls[nb][tid][0] = pbl0;
                *(uint4*)&Bls[nb][tid][4] = pbl1;
            }
            __syncthreads();
            buf = nb;
        }
    }

    // ---- epilogue: bias (+res), row stats, LN, (gelu), store ----
    float s[4] = {0.f, 0.f, 0.f, 0.f}, q[4] = {0.f, 0.f, 0.f, 0.f};
#pragma unroll
    for (int mi = 0; mi < 2; mi++) {
        int lr0 = mi * 16 + g, lr1 = lr0 + 8;
#pragma unroll
        for (int ni = 0; ni < NI; ni++) {
            int c0 = wn + ni * 8 + (t4 << 1);
            float bx = bias[c0], by = bias[c0 + 1];
            float v00 = acc[mi][ni][0] + bx, v01 = acc[mi][ni][1] + by;
            float v10 = acc[mi][ni][2] + bx, v11 = acc[mi][ni][3] + by;
            if (RES) {
                float2 e0 = *(const float2*)(res + (size_t)(m0 + lr0) * W + c0);
                float2 e1 = *(const float2*)(res + (size_t)(m0 + lr1) * W + c0);
                v00 += e0.x; v01 += e0.y; v10 += e1.x; v11 += e1.y;
            }
            acc[mi][ni][0] = v00; acc[mi][ni][1] = v01;
            acc[mi][ni][2] = v10; acc[mi][ni][3] = v11;
            s[mi * 2]     += v00 + v01;       q[mi * 2]     += v00 * v00 + v01 * v01;
            s[mi * 2 + 1] += v10 + v11;       q[mi * 2 + 1] += v10 * v10 + v11 * v11;
        }
    }
#pragma unroll
    for (int i = 0; i < 4; i++) {
        s[i] += __shfl_xor_sync(0xffffffffu, s[i], 1);
        s[i] += __shfl_xor_sync(0xffffffffu, s[i], 2);
        q[i] += __shfl_xor_sync(0xffffffffu, q[i], 1);
        q[i] += __shfl_xor_sync(0xffffffffu, q[i], 2);
    }
    if (t4 == 0) {
#pragma unroll
        for (int mi = 0; mi < 2; mi++) {
            rsum[mi * 16 + g][wid]     = s[mi * 2];
            rsq [mi * 16 + g][wid]     = q[mi * 2];
            rsum[mi * 16 + g + 8][wid] = s[mi * 2 + 1];
            rsq [mi * 16 + g + 8][wid] = q[mi * 2 + 1];
        }
    }
    __syncthreads();
    if (tid < 32) {
        float fs = 0.f, fq = 0.f;
#pragma unroll
        for (int w = 0; w < 8; w++) { fs += rsum[tid][w]; fq += rsq[tid][w]; }
        float mean = fs * (1.0f / W);
        float var = fq * (1.0f / W) - mean * mean;
        smean[tid] = mean;
        sistd[tid] = rsqrtf(var + 1e-5f);
    }
    __syncthreads();

#pragma unroll
    for (int mi = 0; mi < 2; mi++) {
        int lr0 = mi * 16 + g, lr1 = lr0 + 8;
        float m0f = smean[lr0], i0f = sistd[lr0];
        float m1f = smean[lr1], i1f = sistd[lr1];
#pragma unroll
        for (int ni = 0; ni < NI; ni++) {
            int c0 = wn + ni * 8 + (t4 << 1);
            float gx = gam[c0], gy = gam[c0 + 1];
            float bx = bet[c0], by = bet[c0 + 1];
            float o00 = gx * (acc[mi][ni][0] - m0f) * i0f + bx;
            float o01 = gy * (acc[mi][ni][1] - m0f) * i0f + by;
            float o10 = gx * (acc[mi][ni][2] - m1f) * i1f + bx;
            float o11 = gy * (acc[mi][ni][3] - m1f) * i1f + by;
            if (GELU_AFTER) {
                o00 = gelu_f(o00); o01 = gelu_f(o01);
                o10 = gelu_f(o10); o11 = gelu_f(o11);
            }
            if (Cf) {
                *(float2*)(Cf + (size_t)(m0 + lr0) * W + c0) = make_float2(o00, o01);
                *(float2*)(Cf + (size_t)(m0 + lr1) * W + c0) = make_float2(o10, o11);
            }
            if (Ch) {
                unsigned h0, l0, h1, l1;
                packsplit(o00, o01, h0, l0);
                packsplit(o10, o11, h1, l1);
                size_t i0 = (size_t)(m0 + lr0) * (W / 2) + (c0 >> 1);
                size_t i1 = (size_t)(m0 + lr1) * (W / 2) + (c0 >> 1);
                Ch[i0] = h0; Cl[i0] = l0;
                Ch[i1] = h1; Cl[i1] = l1;
            }
        }
    }
}

// ---------------- fused attention: packed bf16 QK + tf32x3 PV ---------------
__global__ void __launch_bounds__(128) attn_fused(const unsigned* __restrict__ QKh,
                                                  const unsigned* __restrict__ QKl,
                                                  const float* __restrict__ V,
                                                  unsigned* __restrict__ Oh,
                                                  unsigned* __restrict__ Ol) {
    __shared__ unsigned Qh[32][72], Ql[32][72];   // [d2][qrow]
    __shared__ unsigned Kh[32][40], Kl[32][40];   // [d2][kpos]
    __shared__ __align__(16) float Vs[32][68];    // [kpos][d]
    __shared__ float Ss[64][36];                  // [q][kpos]
    __shared__ float rm[64], rl[64], rf[64];

    const int b = blockIdx.z, h = blockIdx.y, q0 = blockIdx.x << 6;
    const int tid = threadIdx.x;
    const int lane = tid & 31, wid = tid >> 5;
    const int g = lane >> 2, t4 = lane & 3;

    const unsigned* Qgh = QKh + ((size_t)(b * 512 + q0)) * 128 + h * 32;
    const unsigned* Qgl = QKl + ((size_t)(b * 512 + q0)) * 128 + h * 32;
    const unsigned* Kgh = QKh + (size_t)PTS * 128 + ((size_t)b * 512) * 128 + h * 32;
    const unsigned* Kgl = QKl + (size_t)PTS * 128 + ((size_t)b * 512) * 128 + h * 32;
    const float* Vg = V + ((size_t)b * 512) * 256 + h * 64;

    {
        int qrow = tid >> 1, half = (tid & 1) << 4;
        const uint4* sh = (const uint4*)(Qgh + (size_t)qrow * 128 + half);
        const uint4* sl = (const uint4*)(Qgl + (size_t)qrow * 128 + half);
#pragma unroll
        for (int j = 0; j < 4; j++) {
            uint4 vh = sh[j], vl = sl[j];
            int d2 = half + j * 4;
            Qh[d2 + 0][qrow] = vh.x; Ql[d2 + 0][qrow] = vl.x;
            Qh[d2 + 1][qrow] = vh.y; Ql[d2 + 1][qrow] = vl.y;
            Qh[d2 + 2][qrow] = vh.z; Ql[d2 + 2][qrow] = vl.z;
            Qh[d2 + 3][qrow] = vh.w; Ql[d2 + 3][qrow] = vl.w;
        }
    }
    if (tid < 64) { rm[tid] = -1e30f; rl[tid] = 0.0f; }

    const int wm = (wid >> 1) << 5, wn = (wid & 1) << 5;
    const int sm = wid << 4;
    float oacc[2][4][4] = {};

    for (int kc = 0; kc < 512; kc += 32) {
        __syncthreads();
        {
            int kpos = tid >> 2, seg = (tid & 3) << 3;
            const uint4* sh = (const uint4*)(Kgh + (size_t)(kc + kpos) * 128 + seg);
            const uint4* sl = (const uint4*)(Kgl + (size_t)(kc + kpos) * 128 + seg);
#pragma unroll
            for (int j = 0; j < 2; j++) {
                uint4 vh = sh[j], vl = sl[j];
                int d2 = seg + j * 4;
                Kh[d2 + 0][kpos] = vh.x; Kl[d2 + 0][kpos] = vl.x;
                Kh[d2 + 1][kpos] = vh.y; Kl[d2 + 1][kpos] = vl.y;
                Kh[d2 + 2][kpos] = vh.z; Kl[d2 + 2][kpos] = vl.z;
                Kh[d2 + 3][kpos] = vh.w; Kl[d2 + 3][kpos] = vl.w;
            }
        }
        {
            int i = tid >> 2, d0 = (tid & 3) << 4;
            const float* vsrc = Vg + (size_t)(kc + i) * 256 + d0;
#pragma unroll
            for (int j = 0; j < 4; j++)
                *(float4*)&Vs[i][d0 + j * 4] = *(const float4*)(vsrc + j * 4);
        }
        __syncthreads();

        float sacc[4][4] = {};
#pragma unroll
        for (int kk2 = 0; kk2 < 32; kk2 += 8) {
            int r0 = sm + g, r1 = r0 + 8;
            unsigned a0h = Qh[kk2 + t4][r0],     a0l = Ql[kk2 + t4][r0];
            unsigned a1h = Qh[kk2 + t4][r1],     a1l = Ql[kk2 + t4][r1];
            unsigned a2h = Qh[kk2 + t4 + 4][r0], a2l = Ql[kk2 + t4 + 4][r0];
            unsigned a3h = Qh[kk2 + t4 + 4][r1], a3l = Ql[kk2 + t4 + 4][r1];
#pragma unroll
            for (int ni = 0; ni < 4; ni++) {
                int c = ni * 8 + g;
                unsigned b0h = Kh[kk2 + t4][c],     b0l = Kl[kk2 + t4][c];
                unsigned b1h = Kh[kk2 + t4 + 4][c], b1l = Kl[kk2 + t4 + 4][c];
                mma16(sacc[ni], a0l, a1l, a2l, a3l, b0h, b1h);
                mma16(sacc[ni], a0h, a1h, a2h, a3h, b0l, b1l);
                mma16(sacc[ni], a0h, a1h, a2h, a3h, b0h, b1h);
            }
        }
#pragma unroll
        for (int ni = 0; ni < 4; ni++) {
            int c = (ni << 3) + (t4 << 1);
            Ss[sm + g][c]         = sacc[ni][0] * 0.125f;
            Ss[sm + g][c + 1]     = sacc[ni][1] * 0.125f;
            Ss[sm + g + 8][c]     = sacc[ni][2] * 0.125f;
            Ss[sm + g + 8][c + 1] = sacc[ni][3] * 0.125f;
        }
        __syncthreads();

        if (tid < 64) {
            float mold = rm[tid];
            float mx = mold;
#pragma unroll
            for (int j = 0; j < 32; j++) mx = fmaxf(mx, Ss[tid][j]);
            float f = __expf(mold - mx);
            float sum = 0.0f;
#pragma unroll
            for (int j = 0; j < 32; j++) {
                float p = __expf(Ss[tid][j] - mx);
                Ss[tid][j] = p;
                sum += p;
            }
            rl[tid] = rl[tid] * f + sum;
            rm[tid] = mx;
            rf[tid] = f;
        }
        __syncthreads();

#pragma unroll
        for (int mi = 0; mi < 2; mi++) {
            float f0 = rf[wm + (mi << 4) + g];
            float f1 = rf[wm + (mi << 4) + g + 8];
#pragma unroll
            for (int ni = 0; ni < 4; ni++) {
                oacc[mi][ni][0] *= f0; oacc[mi][ni][1] *= f0;
                oacc[mi][ni][2] *= f1; oacc[mi][ni][3] *= f1;
            }
        }
#pragma unroll
        for (int kk = 0; kk < 32; kk += 8) {
            unsigned ah[2][4], al[2][4];
#pragma unroll
            for (int mi = 0; mi < 2; mi++) {
                split_tf32(Ss[wm + (mi << 4) + g][kk + t4],         ah[mi][0], al[mi][0]);
                split_tf32(Ss[wm + (mi << 4) + g + 8][kk + t4],     ah[mi][1], al[mi][1]);
                split_tf32(Ss[wm + (mi << 4) + g][kk + t4 + 4],     ah[mi][2], al[mi][2]);
                split_tf32(Ss[wm + (mi << 4) + g + 8][kk + t4 + 4], ah[mi][3], al[mi][3]);
            }
#pragma unroll
            for (int ni = 0; ni < 4; ni++) {
                unsigned bh0, bh1, bl0, bl1;
                split_tf32(Vs[kk + t4][wn + ni * 8 + g],     bh0, bl0);
                split_tf32(Vs[kk + t4 + 4][wn + ni * 8 + g], bh1, bl1);
#pragma unroll
                for (int mi = 0; mi < 2; mi++) {
                    float* c = oacc[mi][ni];
                    mma8(c, al[mi][0], al[mi][1], al[mi][2], al[mi][3], bh0, bh1);
                    mma8(c, ah[mi][0], ah[mi][1], ah[mi][2], ah[mi][3], bl0, bl1);
                    mma8(c, ah[mi][0], ah[mi][1], ah[mi][2], ah[mi][3], bh0, bh1);
                }
            }
        }
    }

    // epilogue: normalize + pack O
#pragma unroll
    for (int mi = 0; mi < 2; mi++) {
        int r0 = wm + (mi << 4) + g, r1 = r0 + 8;
        float il0 = 1.0f / rl[r0], il1 = 1.0f / rl[r1];
#pragma unroll
        for (int ni = 0; ni < 4; ni++) {
            int c = wn + (ni << 3) + (t4 << 1);
            unsigned h0, l0, h1, l1;
            packsplit(oacc[mi][ni][0] * il0, oacc[mi][ni][1] * il0, h0, l0);
            packsplit(oacc[mi][ni][2] * il1, oacc[mi][ni][3] * il1, h1, l1);
            size_t i0 = ((size_t)(b * 512 + q0 + r0)) * 128 + h * 32 + (c >> 1);
            size_t i1 = ((size_t)(b * 512 + q0 + r1)) * 128 + h * 32 + (c >> 1);
            Oh[i0] = h0; Ol[i0] = l0;
            Oh[i1] = h1; Ol[i1] = l1;
        }
    }
}

// ---------------- launch ----------------------------------------------------
extern "C" void kernel_launch(void* const* d_in, const int* in_sizes, int n_in,
                              void* d_out, int out_size) {
    (void)in_sizes; (void)n_in; (void)out_size;
    const float* image  = (const float*)d_in[0];
    const float* coords = (const float*)d_in[1];
    const int*   labels = (const int*)d_in[2];
    const float* pe_w   = (const float*)d_in[3];
    const float* pe_b   = (const float*)d_in[4];
    const float* temb   = (const float*)d_in[5];
    const float* fbi    = (const float*)d_in[6];
    const float* fe1_w  = (const float*)d_in[7];
    const float* fe1_b  = (const float*)d_in[8];
    const float* feln1g = (const float*)d_in[9];
    const float* feln1b = (const float*)d_in[10];
    const float* fe2_w  = (const float*)d_in[11];
    const float* fe2_b  = (const float*)d_in[12];
    const float* feln2g = (const float*)d_in[13];
    const float* feln2b = (const float*)d_in[14];
    const float* in_w   = (const float*)d_in[15];
    const float* in_b   = (const float*)d_in[16];
    const float* ao_w   = (const float*)d_in[17];
    const float* ao_b   = (const float*)d_in[18];
    const float* n1_g   = (const float*)d_in[19];
    const float* n1_b   = (const float*)d_in[20];
    const float* f1_w   = (const float*)d_in[21];
    const float* f1_b   = (const float*)d_in[22];
    const float* f2_w   = (const float*)d_in[23];
    const float* f2_b   = (const float*)d_in[24];
    const float* n2_g   = (const float*)d_in[25];
    const float* n2_b   = (const float*)d_in[26];
    const float* op_w   = (const float*)d_in[27];
    const float* op_b   = (const float*)d_in[28];
    float* out = (float*)d_out;

    unsigned *p_peh, *p_pel, *p_feath, *p_featl, *p_spath, *p_spatl;
    unsigned *p_h1h, *p_h1l, *p_freqh, *p_freql, *p_qkh, *p_qkl;
    unsigned *p_oh, *p_ol, *p_xh, *p_xl, *p_ffhh, *p_ffhl, *p_x2h, *p_x2l;
    unsigned *p_wh, *p_wl;
    float *p_spatial, *p_v, *p_x;
    cudaGetSymbolAddress((void**)&p_peh, g_peh);
    cudaGetSymbolAddress((void**)&p_pel, g_pel);
    cudaGetSymbolAddress((void**)&p_feath, g_feath);
    cudaGetSymbolAddress((void**)&p_featl, g_featl);
    cudaGetSymbolAddress((void**)&p_spatial, g_spatial);
    cudaGetSymbolAddress((void**)&p_spath, g_spath);
    cudaGetSymbolAddress((void**)&p_spatl, g_spatl);
    cudaGetSymbolAddress((void**)&p_h1h, g_h1h);
    cudaGetSymbolAddress((void**)&p_h1l, g_h1l);
    cudaGetSymbolAddress((void**)&p_freqh, g_freqh);
    cudaGetSymbolAddress((void**)&p_freql, g_freql);
    cudaGetSymbolAddress((void**)&p_qkh, g_qkh);
    cudaGetSymbolAddress((void**)&p_qkl, g_qkl);
    cudaGetSymbolAddress((void**)&p_v, g_v);
    cudaGetSymbolAddress((void**)&p_oh, g_oh);
    cudaGetSymbolAddress((void**)&p_ol, g_ol);
    cudaGetSymbolAddress((void**)&p_x, g_x);
    cudaGetSymbolAddress((void**)&p_xh, g_xh);
    cudaGetSymbolAddress((void**)&p_xl, g_xl);
    cudaGetSymbolAddress((void**)&p_ffhh, g_ffhh);
    cudaGetSymbolAddress((void**)&p_ffhl, g_ffhl);
    cudaGetSymbolAddress((void**)&p_x2h, g_x2h);
    cudaGetSymbolAddress((void**)&p_x2l, g_x2l);
    cudaGetSymbolAddress((void**)&p_wh, g_wh);
    cudaGetSymbolAddress((void**)&p_wl, g_wl);

    // 1) FFT features + PE + weight packing, one launch
    prep_kernel<<<6144 + 1349, 256>>>(image, coords, fbi, p_feath, p_featl,
        p_peh, p_pel, pe_w, fe1_w, fe2_w, in_w, ao_w, f1_w, f2_w, op_w,
        p_wh, p_wl);
    // 2) spatial = PE @ pe_w^T + bias + temb  -> fp32 + packed
    gemm_p<2><<<dim3(4, 64, 1), 128>>>(p_peh, p_pel, p_wh + OFF_PE, p_wl + OFF_PE,
        pe_b, p_spatial, p_spath, p_spatl, 128, 256, 128, labels, temb,
        nullptr, nullptr);
    // 3) freq MLP (packed GEMM+LN, 8-warp blocks)
    gemm_pln<128, false, true><<<128, 256>>>(p_feath, p_featl,
        p_wh + OFF_FE1, p_wl + OFF_FE1, fe1_b, nullptr, feln1g, feln1b,
        nullptr, p_h1h, p_h1l, 8);
    gemm_pln<256, false, false><<<128, 256>>>(p_h1h, p_h1l,
        p_wh + OFF_FE2, p_wl + OFF_FE2, fe2_b, nullptr, feln2g, feln2b,
        nullptr, p_freqh, p_freql, 64);
    // 4) QKV: z=0,1 -> packed qk; z=2 -> fp32 V
    gemm_p<4><<<dim3(4, 64, 3), 128>>>(p_spath, p_spatl,
        p_wh + OFF_IN, p_wl + OFF_IN, in_b, p_v, p_qkh, p_qkl,
        128, 256, 128, nullptr, nullptr, p_freqh, p_freql);
    // 5) fused attention -> packed O
    attn_fused<<<dim3(8, 4, 8), 128>>>(p_qkh, p_qkl, p_v, p_oh, p_ol);
    // 6) ao + residual + LN -> x fp32 + packed
    gemm_pln<256, true, false><<<128, 256>>>(p_oh, p_ol,
        p_wh + OFF_AO, p_wl + OFF_AO, ao_b, p_spatial, n1_g, n1_b,
        p_x, p_xh, p_xl, 128);
    // 7) FFN up (gelu) -> packed
    gemm_p<1><<<dim3(8, 64, 1), 128>>>(p_xh, p_xl, p_wh + OFF_F1, p_wl + OFF_F1,
        f1_b, nullptr, p_ffhh, p_ffhl, 128, 512, 256, nullptr, nullptr,
        nullptr, nullptr);
    // 8) FFN down + residual + LN -> packed
    gemm_pln<256, true, false><<<128, 256>>>(p_ffhh, p_ffhl,
        p_wh + OFF_F2, p_wl + OFF_F2, f2_b, p_x, n2_g, n2_b,
        nullptr, p_x2h, p_x2l, 256);
    // 9) output projection -> fp32 out
    gemm_p<0><<<dim3(4, 64, 1), 128>>>(p_x2h, p_x2l, p_wh + OFF_OP, p_wl + OFF_OP,
        op_b, out, nullptr, nullptr, 128, 256, 128, nullptr, nullptr,
        nullptr, nullptr);
}

// round 15
// speedup vs baseline: 1.1032x; 1.1032x over previous
#include <cuda_runtime.h>
#include <math.h>

#define PTS 4096      // B*N = 8*512

// ---------------- packed activation / weight scratch -------------------------
__device__ unsigned g_peh[PTS * 128],  g_pel[PTS * 128];
__device__ unsigned g_feath[PTS * 8],  g_featl[PTS * 8];
__device__ float    g_spatial[PTS * 256];
__device__ unsigned g_spath[PTS * 128], g_spatl[PTS * 128];
__device__ unsigned g_h1h[PTS * 64],   g_h1l[PTS * 64];
__device__ unsigned g_freqh[PTS * 128], g_freql[PTS * 128];
__device__ unsigned g_qkh[2u * PTS * 128], g_qkl[2u * PTS * 128];
__device__ float    g_v[PTS * 256];
__device__ unsigned g_oh[PTS * 128],   g_ol[PTS * 128];
__device__ float    g_x[PTS * 256];
__device__ unsigned g_xh[PTS * 128],   g_xl[PTS * 128];
__device__ unsigned g_ffhh[PTS * 256], g_ffhl[PTS * 256];
__device__ unsigned g_x2h[PTS * 128],  g_x2l[PTS * 128];
__device__ unsigned g_wh[345088],      g_wl[345088];

// weight segment offsets (in pairs)
#define OFF_PE   0
#define OFF_FE1  32768
#define OFF_FE2  33792
#define OFF_IN   50176
#define OFF_AO   148480
#define OFF_F1   181248
#define OFF_F2   246784
#define OFF_OP   312320
#define TOT_PAIRS 345088

__device__ __forceinline__ float gelu_f(float x) {
    return 0.5f * x * (1.0f + erff(x * 0.7071067811865475f));
}

// tf32 helpers (attention PV path) -------------------------------------------
__device__ __forceinline__ unsigned tf32_rna(float x) {
    unsigned r;
    asm("cvt.rna.tf32.f32 %0, %1;" : "=r"(r) : "f"(x));
    return r;
}
__device__ __forceinline__ void mma8(float* c, unsigned a0, unsigned a1,
                                     unsigned a2, unsigned a3,
                                     unsigned b0, unsigned b1) {
    asm("mma.sync.aligned.m16n8k8.row.col.f32.tf32.tf32.f32 "
        "{%0,%1,%2,%3},{%4,%5,%6,%7},{%8,%9},{%0,%1,%2,%3};"
        : "+f"(c[0]), "+f"(c[1]), "+f"(c[2]), "+f"(c[3])
        : "r"(a0), "r"(a1), "r"(a2), "r"(a3), "r"(b0), "r"(b1));
}
__device__ __forceinline__ void split_tf32(float x, unsigned& hi, unsigned& lo) {
    hi = tf32_rna(x);
    lo = __float_as_uint(x - __uint_as_float(hi));
}

// bf16x2 helpers --------------------------------------------------------------
__device__ __forceinline__ void packsplit(float x0, float x1,
                                          unsigned& h, unsigned& l) {
    unsigned hh;
    asm("cvt.rn.bf16x2.f32 %0, %1, %2;" : "=r"(hh) : "f"(x1), "f"(x0));
    float r0 = x0 - __uint_as_float(hh << 16);
    float r1 = x1 - __uint_as_float(hh & 0xffff0000u);
    asm("cvt.rn.bf16x2.f32 %0, %1, %2;" : "=r"(l) : "f"(r1), "f"(r0));
    h = hh;
}
__device__ __forceinline__ void mma16(float* c,
                                      unsigned a0, unsigned a1, unsigned a2, unsigned a3,
                                      unsigned b0, unsigned b1) {
    asm("mma.sync.aligned.m16n8k16.row.col.f32.bf16.bf16.f32 "
        "{%0,%1,%2,%3},{%4,%5,%6,%7},{%8,%9},{%0,%1,%2,%3};"
        : "+f"(c[0]), "+f"(c[1]), "+f"(c[2]), "+f"(c[3])
        : "r"(a0), "r"(a1), "r"(a2), "r"(a3), "r"(b0), "r"(b1));
}
__device__ __forceinline__ void mma_x3p(float* c,
                                        unsigned a0h, unsigned a1h, unsigned a2h, unsigned a3h,
                                        unsigned a0l, unsigned a1l, unsigned a2l, unsigned a3l,
                                        unsigned b0h, unsigned b1h,
                                        unsigned b0l, unsigned b1l) {
    mma16(c, a0l, a1l, a2l, a3l, b0h, b1h);
    mma16(c, a0h, a1h, a2h, a3h, b0l, b1l);
    mma16(c, a0h, a1h, a2h, a3h, b0h, b1h);
}

// ---------------- prep: FFT feat (0..4095) | PE (4096..6143) | pack W -------
__global__ void __launch_bounds__(256) prep_kernel(
    const float* __restrict__ image, const float* __restrict__ coords,
    const float* __restrict__ fbi,
    unsigned* __restrict__ feath, unsigned* __restrict__ featl,
    unsigned* __restrict__ peh, unsigned* __restrict__ pel,
    const float* __restrict__ pe_w, const float* __restrict__ fe1_w,
    const float* __restrict__ fe2_w, const float* __restrict__ in_w,
    const float* __restrict__ ao_w, const float* __restrict__ f1_w,
    const float* __restrict__ f2_w, const float* __restrict__ op_w,
    unsigned* __restrict__ wh, unsigned* __restrict__ wl)
{
    int tid = threadIdx.x;
    if (blockIdx.x >= 6144) {
        int p = (blockIdx.x - 6144) * 256 + tid;
        if (p < TOT_PAIRS) {
            const float* src;
            if      (p < OFF_FE1) src = pe_w  + (size_t)(p - OFF_PE) * 2;
            else if (p < OFF_FE2) src = fe1_w + (size_t)(p - OFF_FE1) * 2;
            else if (p < OFF_IN)  src = fe2_w + (size_t)(p - OFF_FE2) * 2;
            else if (p < OFF_AO)  src = in_w  + (size_t)(p - OFF_IN) * 2;
            else if (p < OFF_F1)  src = ao_w  + (size_t)(p - OFF_AO) * 2;
            else if (p < OFF_F2)  src = f1_w  + (size_t)(p - OFF_F1) * 2;
            else if (p < OFF_OP)  src = f2_w  + (size_t)(p - OFF_F2) * 2;
            else                  src = op_w  + (size_t)(p - OFF_OP) * 2;
            float2 v = *(const float2*)src;
            packsplit(v.x, v.y, wh[p], wl[p]);
        }
        return;
    }
    if (blockIdx.x >= 4096) {
        int idx = blockIdx.x - 4096;
        int pt = idx * 2 + (tid >> 7);
        int p = tid & 127;
        int region = p >> 5;
        int comp = p >> 6;
        int i0 = (2 * p) & 63;
        float c = coords[pt * 2 + comp] * (1.0f / 1024.0f);
        float a0 = c * 6.283185307179586f * exp2f(-(float)i0 * 0.4152410118609203f);
        float a1 = c * 6.283185307179586f * exp2f(-(float)(i0 + 1) * 0.4152410118609203f);
        float s0, c0, s1, c1;
        sincosf(a0, &s0, &c0);
        sincosf(a1, &s1, &c1);
        float v0 = (region & 1) ? c0 : s0;
        float v1 = (region & 1) ? c1 : s1;
        packsplit(v0, v1, peh[(size_t)pt * 128 + p], pel[(size_t)pt * 128 + p]);
        return;
    }

    int pt = blockIdx.x;
    int b = pt >> 9;

    __shared__ float patch[16][16];
    __shared__ float Rre[16][9], Rim[16][9];
    __shared__ float twc[16], tws[16];
    __shared__ float bmag[8], bang[8];
    __shared__ int bcnt[8];
    __shared__ float smf[8];
    __shared__ float fv[16];
    __shared__ int spx, spy;

    if (tid == 0) {
        float cx = coords[pt * 2];
        float cy = coords[pt * 2 + 1];
        int px = (int)cx; px = min(max(px, 8), 1015);
        int py = (int)cy; py = min(max(py, 8), 1015);
        spx = px; spy = py;
        float mx = -1e30f;
        for (int i = 0; i < 8; i++) mx = fmaxf(mx, fbi[i]);
        float s = 0.0f;
        for (int i = 0; i < 8; i++) { float e = expf(fbi[i] - mx); smf[i] = e; s += e; }
        float inv = 1.0f / s;
        for (int i = 0; i < 8; i++) smf[i] *= inv;
    }
    if (tid < 16) {
        twc[tid] = cospif((float)tid / 8.0f);
        tws[tid] = sinpif(-(float)tid / 8.0f);
    }
    if (tid < 8) { bmag[tid] = 0.0f; bang[tid] = 0.0f; bcnt[tid] = 0; }
    __syncthreads();

    int y = tid >> 4, x = tid & 15;
    int yy = spy - 8 + y, xx = spx - 8 + x;
    const float* imb = image + (size_t)b * 3u * 1024u * 1024u;
    size_t off = (size_t)yy * 1024 + xx;
    float gsum = imb[off] + imb[1048576u + off] + imb[2097152u + off];
    patch[y][x] = gsum * (1.0f / 3.0f);
    __syncthreads();

    if (tid < 144) {
        int ry = tid / 9, kx = tid % 9;
        float re = 0.0f, im = 0.0f;
#pragma unroll
        for (int j = 0; j < 16; j++) {
            float pv = patch[ry][j];
            int t = (kx * j) & 15;
            re += pv * twc[t];
            im += pv * tws[t];
        }
        Rre[ry][kx] = re;
        Rim[ry][kx] = im;
    }
    __syncthreads();

    if (tid < 144) {
        int ky = tid / 9, kx = tid % 9;
        float re = 0.0f, im = 0.0f;
#pragma unroll
        for (int j = 0; j < 16; j++) {
            int t = (ky * j) & 15;
            float c = twc[t], s = tws[t];
            float ar = Rre[j][kx], ai = Rim[j][kx];
            re += ar * c - ai * s;
            im += ar * s + ai * c;
        }
        re *= 0.0625f;
        im *= 0.0625f;
        float mag = sqrtf(re * re + im * im);
        float ang = atan2f(im, re);

        double fy = (ky < 8) ? (double)ky / 16.0 : ((double)ky - 16.0) / 16.0;
        double fx = (double)kx / 16.0;
        double r = sqrt(fx * fx + fy * fy);
        double maxr = 0.7071067811865476 + 1e-6;
        double step = maxr / 8.0;
        int bi = 0;
#pragma unroll
        for (int k = 1; k < 9; k++) if (r >= (double)k * step) bi = k;
        if (bi > 7) bi = 7;
        atomicAdd(&bmag[bi], mag);
        atomicAdd(&bang[bi], ang);
        atomicAdd(&bcnt[bi], 1);
    }
    __syncthreads();

    if (tid < 8) {
        float c = (float)max(bcnt[tid], 1);
        fv[tid]     = bmag[tid] / c * smf[tid];
        fv[8 + tid] = bang[tid] / c;
    }
    __syncthreads();
    if (tid < 8) {
        packsplit(fv[2 * tid], fv[2 * tid + 1],
                  feath[(size_t)pt * 8 + tid], featl[(size_t)pt * 8 + tid]);
    }
}

// ---------------- packed bf16x3 GEMM: C = A @ B^T + bias --------------------
// 64x64 tile, 128 threads (2x2 warps), double-buffered, [row][12] smem
// (pitch 12 -> conflict-free fragment LDS).
template <int EP>
__global__ void __launch_bounds__(128) gemm_p(
    const unsigned* __restrict__ Ah, const unsigned* __restrict__ Al,
    const unsigned* __restrict__ Bh, const unsigned* __restrict__ Bl,
    const float* __restrict__ bias,
    float* __restrict__ Cf, unsigned* __restrict__ Ch, unsigned* __restrict__ Cl,
    int K2, int ldcF, int ldp,
    const int* __restrict__ labels, const float* __restrict__ temb,
    const unsigned* __restrict__ A2h, const unsigned* __restrict__ A2l)
{
    __shared__ unsigned Ahs[2][64][12], Als[2][64][12];
    __shared__ unsigned Bhs[2][64][12], Bls[2][64][12];

    int z = 0;
    if (EP == 4) {
        z = blockIdx.z;
        if (z > 0) { Ah = A2h; Al = A2l; }
        Bh += (size_t)z * 32768;
        Bl += (size_t)z * 32768;
        bias += z << 8;
    }

    const int tid = threadIdx.x;
    const int m0 = blockIdx.y << 6, n0 = blockIdx.x << 6;
    const int srow = tid >> 1, sseg = (tid & 1) << 2;

    const unsigned* Aph = Ah + (size_t)(m0 + srow) * K2 + sseg;
    const unsigned* Apl = Al + (size_t)(m0 + srow) * K2 + sseg;
    const unsigned* Bph = Bh + (size_t)(n0 + srow) * K2 + sseg;
    const unsigned* Bpl = Bl + (size_t)(n0 + srow) * K2 + sseg;

    const int lane = tid & 31, wid = tid >> 5;
    const int g = lane >> 2, t4 = lane & 3;
    const int wm = (wid >> 1) << 5, wn = (wid & 1) << 5;

    float acc[2][4][4] = {};

    *(uint4*)&Ahs[0][srow][sseg] = *(const uint4*)Aph;
    *(uint4*)&Als[0][srow][sseg] = *(const uint4*)Apl;
    *(uint4*)&Bhs[0][srow][sseg] = *(const uint4*)Bph;
    *(uint4*)&Bls[0][srow][sseg] = *(const uint4*)Bpl;
    __syncthreads();

    int buf = 0;
    for (int k20 = 0; k20 < K2; k20 += 8) {
        const bool notlast = (k20 + 8 < K2);
        uint4 pah, pal, pbh, pbl;
        if (notlast) {
            pah = *(const uint4*)(Aph + k20 + 8);
            pal = *(const uint4*)(Apl + k20 + 8);
            pbh = *(const uint4*)(Bph + k20 + 8);
            pbl = *(const uint4*)(Bpl + k20 + 8);
        }

        unsigned bh0[4], bh1[4], bl0[4], bl1[4];
#pragma unroll
        for (int ni = 0; ni < 4; ni++) {
            int c = wn + ni * 8 + g;
            bh0[ni] = Bhs[buf][c][t4];     bl0[ni] = Bls[buf][c][t4];
            bh1[ni] = Bhs[buf][c][t4 + 4]; bl1[ni] = Bls[buf][c][t4 + 4];
        }
#pragma unroll
        for (int mi = 0; mi < 2; mi++) {
            int r0 = wm + mi * 16 + g, r1 = r0 + 8;
            unsigned a0h = Ahs[buf][r0][t4],     a0l = Als[buf][r0][t4];
            unsigned a1h = Ahs[buf][r1][t4],     a1l = Als[buf][r1][t4];
            unsigned a2h = Ahs[buf][r0][t4 + 4], a2l = Als[buf][r0][t4 + 4];
            unsigned a3h = Ahs[buf][r1][t4 + 4], a3l = Als[buf][r1][t4 + 4];
#pragma unroll
            for (int ni = 0; ni < 4; ni++)
                mma_x3p(acc[mi][ni], a0h, a1h, a2h, a3h, a0l, a1l, a2l, a3l,
                        bh0[ni], bh1[ni], bl0[ni], bl1[ni]);
        }

        if (notlast) {
            int nb = buf ^ 1;
            *(uint4*)&Ahs[nb][srow][sseg] = pah;
            *(uint4*)&Als[nb][srow][sseg] = pal;
            *(uint4*)&Bhs[nb][srow][sseg] = pbh;
            *(uint4*)&Bls[nb][srow][sseg] = pbl;
            __syncthreads();
            buf = nb;
        }
    }

#pragma unroll
    for (int mi = 0; mi < 2; mi++) {
        int r0 = m0 + wm + mi * 16 + g;
        int r1 = r0 + 8;
        const float* t0 = nullptr;
        const float* t1 = nullptr;
        if (EP == 2) {
            t0 = temb + (size_t)labels[r0] * 256;
            t1 = temb + (size_t)labels[r1] * 256;
        }
#pragma unroll
        for (int ni = 0; ni < 4; ni++) {
            int c0 = n0 + wn + ni * 8 + (t4 << 1);
            float v00 = acc[mi][ni][0], v01 = acc[mi][ni][1];
            float v10 = acc[mi][ni][2], v11 = acc[mi][ni][3];
            float bx = bias[c0], by = bias[c0 + 1];
            v00 += bx; v01 += by; v10 += bx; v11 += by;
            if (EP == 1) {
                v00 = gelu_f(v00); v01 = gelu_f(v01);
                v10 = gelu_f(v10); v11 = gelu_f(v11);
            }
            if (EP == 2) {
                v00 += t0[c0]; v01 += t0[c0 + 1];
                v10 += t1[c0]; v11 += t1[c0 + 1];
            }
            if (EP == 4) {
                if (z < 2) {
                    unsigned h0, l0, h1, l1;
                    packsplit(v00, v01, h0, l0);
                    packsplit(v10, v11, h1, l1);
                    size_t i0 = ((size_t)z * PTS + r0) * 128 + (c0 >> 1);
                    size_t i1 = ((size_t)z * PTS + r1) * 128 + (c0 >> 1);
                    Ch[i0] = h0; Cl[i0] = l0;
                    Ch[i1] = h1; Cl[i1] = l1;
                } else {
                    *(float2*)(Cf + (size_t)r0 * ldcF + c0) = make_float2(v00, v01);
                    *(float2*)(Cf + (size_t)r1 * ldcF + c0) = make_float2(v10, v11);
                }
            } else {
                if (Cf) {
                    *(float2*)(Cf + (size_t)r0 * ldcF + c0) = make_float2(v00, v01);
                    *(float2*)(Cf + (size_t)r1 * ldcF + c0) = make_float2(v10, v11);
                }
                if (Ch) {
                    unsigned h0, l0, h1, l1;
                    packsplit(v00, v01, h0, l0);
                    packsplit(v10, v11, h1, l1);
                    size_t i0 = (size_t)r0 * ldp + (c0 >> 1);
                    size_t i1 = (size_t)r1 * ldp + (c0 >> 1);
                    Ch[i0] = h0; Cl[i0] = l0;
                    Ch[i1] = h1; Cl[i1] = l1;
                }
            }
        }
    }
}

// ---------------- packed GEMM + fused LayerNorm: 32 x W tile, 4 warps -------
// A pitch 12; B k-major transposed [8][W+8] -> conflict-free fragment LDS.
template <int W, bool RES, bool GELU_AFTER>
__global__ void __launch_bounds__(128) gemm_pln(
    const unsigned* __restrict__ Ah, const unsigned* __restrict__ Al,
    const unsigned* __restrict__ Bh, const unsigned* __restrict__ Bl,
    const float* __restrict__ bias, const float* __restrict__ res,
    const float* __restrict__ gam, const float* __restrict__ bet,
    float* __restrict__ Cf, unsigned* __restrict__ Ch, unsigned* __restrict__ Cl,
    int K2)
{
    constexpr int NI = W / 32;
    __shared__ unsigned Ahs[2][32][12], Als[2][32][12];
    __shared__ unsigned Bhs[2][8][W + 8], Bls[2][8][W + 8];
    __shared__ float rsum[32][4], rsq[32][4];
    __shared__ float smean[32], sistd[32];

    const int tid = threadIdx.x;
    const int m0 = blockIdx.x << 5;

    const int arow = tid >> 2, aseg = (tid & 3) << 1;
    const unsigned* Aph = Ah + (size_t)(m0 + arow) * K2 + aseg;
    const unsigned* Apl = Al + (size_t)(m0 + arow) * K2 + aseg;
    const int brow = tid >> 1, bseg = (tid & 1) << 2;

    const int lane = tid & 31, wid = tid >> 5;
    const int g = lane >> 2, t4 = lane & 3;
    const int wn = wid * (W / 4);

    float acc[2][NI][4] = {};

    {   // preload tile 0
        uint2 ah2 = *(const uint2*)Aph;
        uint2 al2 = *(const uint2*)Apl;
        Ahs[0][arow][aseg] = ah2.x; Ahs[0][arow][aseg + 1] = ah2.y;
        Als[0][arow][aseg] = al2.x; Als[0][arow][aseg + 1] = al2.y;
#pragma unroll
        for (int j = 0; j < W / 64; j++) {
            int r = brow + 64 * j;
            uint4 bh4 = *(const uint4*)(Bh + (size_t)r * K2 + bseg);
            uint4 bl4 = *(const uint4*)(Bl + (size_t)r * K2 + bseg);
            Bhs[0][bseg + 0][r] = bh4.x; Bhs[0][bseg + 1][r] = bh4.y;
            Bhs[0][bseg + 2][r] = bh4.z; Bhs[0][bseg + 3][r] = bh4.w;
            Bls[0][bseg + 0][r] = bl4.x; Bls[0][bseg + 1][r] = bl4.y;
            Bls[0][bseg + 2][r] = bl4.z; Bls[0][bseg + 3][r] = bl4.w;
        }
    }
    __syncthreads();

    int buf = 0;
    for (int k20 = 0; k20 < K2; k20 += 8) {
        const bool notlast = (k20 + 8 < K2);
        uint2 pah, pal;
        uint4 pbh[W / 64], pbl[W / 64];
        if (notlast) {
            pah = *(const uint2*)(Aph + k20 + 8);
            pal = *(const uint2*)(Apl + k20 + 8);
#pragma unroll
            for (int j = 0; j < W / 64; j++) {
                int r = brow + 64 * j;
                pbh[j] = *(const uint4*)(Bh + (size_t)r * K2 + k20 + 8 + bseg);
                pbl[j] = *(const uint4*)(Bl + (size_t)r * K2 + k20 + 8 + bseg);
            }
        }

        unsigned a0h[2], a1h[2], a2h[2], a3h[2], a0l[2], a1l[2], a2l[2], a3l[2];
#pragma unroll
        for (int mi = 0; mi < 2; mi++) {
            int r0 = mi * 16 + g, r1 = r0 + 8;
            a0h[mi] = Ahs[buf][r0][t4];     a0l[mi] = Als[buf][r0][t4];
            a1h[mi] = Ahs[buf][r1][t4];     a1l[mi] = Als[buf][r1][t4];
            a2h[mi] = Ahs[buf][r0][t4 + 4]; a2l[mi] = Als[buf][r0][t4 + 4];
            a3h[mi] = Ahs[buf][r1][t4 + 4]; a3l[mi] = Als[buf][r1][t4 + 4];
        }
#pragma unroll
        for (int ni = 0; ni < NI; ni++) {
            int c = wn + ni * 8 + g;
            unsigned bh0 = Bhs[buf][t4][c],     bl0 = Bls[buf][t4][c];
            unsigned bh1 = Bhs[buf][t4 + 4][c], bl1 = Bls[buf][t4 + 4][c];
#pragma unroll
            for (int mi = 0; mi < 2; mi++)
                mma_x3p(acc[mi][ni], a0h[mi], a1h[mi], a2h[mi], a3h[mi],
                        a0l[mi], a1l[mi], a2l[mi], a3l[mi], bh0, bh1, bl0, bl1);
        }

        if (notlast) {
            int nb = buf ^ 1;
            Ahs[nb][arow][aseg] = pah.x; Ahs[nb][arow][aseg + 1] = pah.y;
            Als[nb][arow][aseg] = pal.x; Als[nb][arow][aseg + 1] = pal.y;
#pragma unroll
            for (int j = 0; j < W / 64; j++) {
                int r = brow + 64 * j;
                Bhs[nb][bseg + 0][r] = pbh[j].x; Bhs[nb][bseg + 1][r] = pbh[j].y;
                Bhs[nb][bseg + 2][r] = pbh[j].z; Bhs[nb][bseg + 3][r] = pbh[j].w;
                Bls[nb][bseg + 0][r] = pbl[j].x; Bls[nb][bseg + 1][r] = pbl[j].y;
                Bls[nb][bseg + 2][r] = pbl[j].z; Bls[nb][bseg + 3][r] = pbl[j].w;
            }
            __syncthreads();
            buf = nb;
        }
    }

    // ---- epilogue: bias (+res), row stats, LN, (gelu), store ----
    float s[4] = {0.f, 0.f, 0.f, 0.f}, q[4] = {0.f, 0.f, 0.f, 0.f};
#pragma unroll
    for (int mi = 0; mi < 2; mi++) {
        int lr0 = mi * 16 + g, lr1 = lr0 + 8;
#pragma unroll
        for (int ni = 0; ni < NI; ni++) {
            int c0 = wn + ni * 8 + (t4 << 1);
            float bx = bias[c0], by = bias[c0 + 1];
            float v00 = acc[mi][ni][0] + bx, v01 = acc[mi][ni][1] + by;
            float v10 = acc[mi][ni][2] + bx, v11 = acc[mi][ni][3] + by;
            if (RES) {
                float2 e0 = *(const float2*)(res + (size_t)(m0 + lr0) * W + c0);
                float2 e1 = *(const float2*)(res + (size_t)(m0 + lr1) * W + c0);
                v00 += e0.x; v01 += e0.y; v10 += e1.x; v11 += e1.y;
            }
            acc[mi][ni][0] = v00; acc[mi][ni][1] = v01;
            acc[mi][ni][2] = v10; acc[mi][ni][3] = v11;
            s[mi * 2]     += v00 + v01;       q[mi * 2]     += v00 * v00 + v01 * v01;
            s[mi * 2 + 1] += v10 + v11;       q[mi * 2 + 1] += v10 * v10 + v11 * v11;
        }
    }
#pragma unroll
    for (int i = 0; i < 4; i++) {
        s[i] += __shfl_xor_sync(0xffffffffu, s[i], 1);
        s[i] += __shfl_xor_sync(0xffffffffu, s[i], 2);
        q[i] += __shfl_xor_sync(0xffffffffu, q[i], 1);
        q[i] += __shfl_xor_sync(0xffffffffu, q[i], 2);
    }
    if (t4 == 0) {
#pragma unroll
        for (int mi = 0; mi < 2; mi++) {
            rsum[mi * 16 + g][wid]     = s[mi * 2];
            rsq [mi * 16 + g][wid]     = q[mi * 2];
            rsum[mi * 16 + g + 8][wid] = s[mi * 2 + 1];
            rsq [mi * 16 + g + 8][wid] = q[mi * 2 + 1];
        }
    }
    __syncthreads();
    if (tid < 32) {
        float fs = rsum[tid][0] + rsum[tid][1] + rsum[tid][2] + rsum[tid][3];
        float fq = rsq[tid][0] + rsq[tid][1] + rsq[tid][2] + rsq[tid][3];
        float mean = fs * (1.0f / W);
        float var = fq * (1.0f / W) - mean * mean;
        smean[tid] = mean;
        sistd[tid] = rsqrtf(var + 1e-5f);
    }
    __syncthreads();

#pragma unroll
    for (int mi = 0; mi < 2; mi++) {
        int lr0 = mi * 16 + g, lr1 = lr0 + 8;
        float m0f = smean[lr0], i0f = sistd[lr0];
        float m1f = smean[lr1], i1f = sistd[lr1];
#pragma unroll
        for (int ni = 0; ni < NI; ni++) {
            int c0 = wn + ni * 8 + (t4 << 1);
            float gx = gam[c0], gy = gam[c0 + 1];
            float bx = bet[c0], by = bet[c0 + 1];
            float o00 = gx * (acc[mi][ni][0] - m0f) * i0f + bx;
            float o01 = gy * (acc[mi][ni][1] - m0f) * i0f + by;
            float o10 = gx * (acc[mi][ni][2] - m1f) * i1f + bx;
            float o11 = gy * (acc[mi][ni][3] - m1f) * i1f + by;
            if (GELU_AFTER) {
                o00 = gelu_f(o00); o01 = gelu_f(o01);
                o10 = gelu_f(o10); o11 = gelu_f(o11);
            }
            if (Cf) {
                *(float2*)(Cf + (size_t)(m0 + lr0) * W + c0) = make_float2(o00, o01);
                *(float2*)(Cf + (size_t)(m0 + lr1) * W + c0) = make_float2(o10, o11);
            }
            if (Ch) {
                unsigned h0, l0, h1, l1;
                packsplit(o00, o01, h0, l0);
                packsplit(o10, o11, h1, l1);
                size_t i0 = (size_t)(m0 + lr0) * (W / 2) + (c0 >> 1);
                size_t i1 = (size_t)(m0 + lr1) * (W / 2) + (c0 >> 1);
                Ch[i0] = h0; Cl[i0] = l0;
                Ch[i1] = h1; Cl[i1] = l1;
            }
        }
    }
}

// ---------------- fused attention: packed bf16 QK + tf32x3 PV ---------------
__global__ void __launch_bounds__(128) attn_fused(const unsigned* __restrict__ QKh,
                                                  const unsigned* __restrict__ QKl,
                                                  const float* __restrict__ V,
                                                  unsigned* __restrict__ Oh,
                                                  unsigned* __restrict__ Ol) {
    __shared__ unsigned Qh[32][72], Ql[32][72];   // [d2][qrow]
    __shared__ unsigned Kh[32][40], Kl[32][40];   // [d2][kpos]
    __shared__ __align__(16) float Vs[32][68];    // [kpos][d]
    __shared__ float Ss[64][36];                  // [q][kpos]
    __shared__ float rm[64], rl[64], rf[64];

    const int b = blockIdx.z, h = blockIdx.y, q0 = blockIdx.x << 6;
    const int tid = threadIdx.x;
    const int lane = tid & 31, wid = tid >> 5;
    const int g = lane >> 2, t4 = lane & 3;

    const unsigned* Qgh = QKh + ((size_t)(b * 512 + q0)) * 128 + h * 32;
    const unsigned* Qgl = QKl + ((size_t)(b * 512 + q0)) * 128 + h * 32;
    const unsigned* Kgh = QKh + (size_t)PTS * 128 + ((size_t)b * 512) * 128 + h * 32;
    const unsigned* Kgl = QKl + (size_t)PTS * 128 + ((size_t)b * 512) * 128 + h * 32;
    const float* Vg = V + ((size_t)b * 512) * 256 + h * 64;

    {
        int qrow = tid >> 1, half = (tid & 1) << 4;
        const uint4* sh = (const uint4*)(Qgh + (size_t)qrow * 128 + half);
        const uint4* sl = (const uint4*)(Qgl + (size_t)qrow * 128 + half);
#pragma unroll
        for (int j = 0; j < 4; j++) {
            uint4 vh = sh[j], vl = sl[j];
            int d2 = half + j * 4;
            Qh[d2 + 0][qrow] = vh.x; Ql[d2 + 0][qrow] = vl.x;
            Qh[d2 + 1][qrow] = vh.y; Ql[d2 + 1][qrow] = vl.y;
            Qh[d2 + 2][qrow] = vh.z; Ql[d2 + 2][qrow] = vl.z;
            Qh[d2 + 3][qrow] = vh.w; Ql[d2 + 3][qrow] = vl.w;
        }
    }
    if (tid < 64) { rm[tid] = -1e30f; rl[tid] = 0.0f; }

    const int wm = (wid >> 1) << 5, wn = (wid & 1) << 5;
    const int sm = wid << 4;
    float oacc[2][4][4] = {};

    for (int kc = 0; kc < 512; kc += 32) {
        __syncthreads();
        {
            int kpos = tid >> 2, seg = (tid & 3) << 3;
            const uint4* sh = (const uint4*)(Kgh + (size_t)(kc + kpos) * 128 + seg);
            const uint4* sl = (const uint4*)(Kgl + (size_t)(kc + kpos) * 128 + seg);
#pragma unroll
            for (int j = 0; j < 2; j++) {
                uint4 vh = sh[j], vl = sl[j];
                int d2 = seg + j * 4;
                Kh[d2 + 0][kpos] = vh.x; Kl[d2 + 0][kpos] = vl.x;
                Kh[d2 + 1][kpos] = vh.y; Kl[d2 + 1][kpos] = vl.y;
                Kh[d2 + 2][kpos] = vh.z; Kl[d2 + 2][kpos] = vl.z;
                Kh[d2 + 3][kpos] = vh.w; Kl[d2 + 3][kpos] = vl.w;
            }
        }
        {
            int i = tid >> 2, d0 = (tid & 3) << 4;
            const float* vsrc = Vg + (size_t)(kc + i) * 256 + d0;
#pragma unroll
            for (int j = 0; j < 4; j++)
                *(float4*)&Vs[i][d0 + j * 4] = *(const float4*)(vsrc + j * 4);
        }
        __syncthreads();

        float sacc[4][4] = {};
#pragma unroll
        for (int kk2 = 0; kk2 < 32; kk2 += 8) {
            int r0 = sm + g, r1 = r0 + 8;
            unsigned a0h = Qh[kk2 + t4][r0],     a0l = Ql[kk2 + t4][r0];
            unsigned a1h = Qh[kk2 + t4][r1],     a1l = Ql[kk2 + t4][r1];
            unsigned a2h = Qh[kk2 + t4 + 4][r0], a2l = Ql[kk2 + t4 + 4][r0];
            unsigned a3h = Qh[kk2 + t4 + 4][r1], a3l = Ql[kk2 + t4 + 4][r1];
#pragma unroll
            for (int ni = 0; ni < 4; ni++) {
                int c = ni * 8 + g;
                unsigned b0h = Kh[kk2 + t4][c],     b0l = Kl[kk2 + t4][c];
                unsigned b1h = Kh[kk2 + t4 + 4][c], b1l = Kl[kk2 + t4 + 4][c];
                mma16(sacc[ni], a0l, a1l, a2l, a3l, b0h, b1h);
                mma16(sacc[ni], a0h, a1h, a2h, a3h, b0l, b1l);
                mma16(sacc[ni], a0h, a1h, a2h, a3h, b0h, b1h);
            }
        }
#pragma unroll
        for (int ni = 0; ni < 4; ni++) {
            int c = (ni << 3) + (t4 << 1);
            Ss[sm + g][c]         = sacc[ni][0] * 0.125f;
            Ss[sm + g][c + 1]     = sacc[ni][1] * 0.125f;
            Ss[sm + g + 8][c]     = sacc[ni][2] * 0.125f;
            Ss[sm + g + 8][c + 1] = sacc[ni][3] * 0.125f;
        }
        __syncthreads();

        if (tid < 64) {
            float mold = rm[tid];
            float mx = mold;
#pragma unroll
            for (int j = 0; j < 32; j++) mx = fmaxf(mx, Ss[tid][j]);
            float f = __expf(mold - mx);
            float sum = 0.0f;
#pragma unroll
            for (int j = 0; j < 32; j++) {
                float p = __expf(Ss[tid][j] - mx);
                Ss[tid][j] = p;
                sum += p;
            }
            rl[tid] = rl[tid] * f + sum;
            rm[tid] = mx;
            rf[tid] = f;
        }
        __syncthreads();

#pragma unroll
        for (int mi = 0; mi < 2; mi++) {
            float f0 = rf[wm + (mi << 4) + g];
            float f1 = rf[wm + (mi << 4) + g + 8];
#pragma unroll
            for (int ni = 0; ni < 4; ni++) {
                oacc[mi][ni][0] *= f0; oacc[mi][ni][1] *= f0;
                oacc[mi][ni][2] *= f1; oacc[mi][ni][3] *= f1;
            }
        }
#pragma unroll
        for (int kk = 0; kk < 32; kk += 8) {
            unsigned ah[2][4], al[2][4];
#pragma unroll
            for (int mi = 0; mi < 2; mi++) {
                split_tf32(Ss[wm + (mi << 4) + g][kk + t4],         ah[mi][0], al[mi][0]);
                split_tf32(Ss[wm + (mi << 4) + g + 8][kk + t4],     ah[mi][1], al[mi][1]);
                split_tf32(Ss[wm + (mi << 4) + g][kk + t4 + 4],     ah[mi][2], al[mi][2]);
                split_tf32(Ss[wm + (mi << 4) + g + 8][kk + t4 + 4], ah[mi][3], al[mi][3]);
            }
#pragma unroll
            for (int ni = 0; ni < 4; ni++) {
                unsigned bh0, bh1, bl0, bl1;
                split_tf32(Vs[kk + t4][wn + ni * 8 + g],     bh0, bl0);
                split_tf32(Vs[kk + t4 + 4][wn + ni * 8 + g], bh1, bl1);
#pragma unroll
                for (int mi = 0; mi < 2; mi++) {
                    float* c = oacc[mi][ni];
                    mma8(c, al[mi][0], al[mi][1], al[mi][2], al[mi][3], bh0, bh1);
                    mma8(c, ah[mi][0], ah[mi][1], ah[mi][2], ah[mi][3], bl0, bl1);
                    mma8(c, ah[mi][0], ah[mi][1], ah[mi][2], ah[mi][3], bh0, bh1);
                }
            }
        }
    }

    // epilogue: normalize + pack O
#pragma unroll
    for (int mi = 0; mi < 2; mi++) {
        int r0 = wm + (mi << 4) + g, r1 = r0 + 8;
        float il0 = 1.0f / rl[r0], il1 = 1.0f / rl[r1];
#pragma unroll
        for (int ni = 0; ni < 4; ni++) {
            int c = wn + (ni << 3) + (t4 << 1);
            unsigned h0, l0, h1, l1;
            packsplit(oacc[mi][ni][0] * il0, oacc[mi][ni][1] * il0, h0, l0);
            packsplit(oacc[mi][ni][2] * il1, oacc[mi][ni][3] * il1, h1, l1);
            size_t i0 = ((size_t)(b * 512 + q0 + r0)) * 128 + h * 32 + (c >> 1);
            size_t i1 = ((size_t)(b * 512 + q0 + r1)) * 128 + h * 32 + (c >> 1);
            Oh[i0] = h0; Ol[i0] = l0;
            Oh[i1] = h1; Ol[i1] = l1;
        }
    }
}

// ---------------- launch ----------------------------------------------------
extern "C" void kernel_launch(void* const* d_in, const int* in_sizes, int n_in,
                              void* d_out, int out_size) {
    (void)in_sizes; (void)n_in; (void)out_size;
    const float* image  = (const float*)d_in[0];
    const float* coords = (const float*)d_in[1];
    const int*   labels = (const int*)d_in[2];
    const float* pe_w   = (const float*)d_in[3];
    const float* pe_b   = (const float*)d_in[4];
    const float* temb   = (const float*)d_in[5];
    const float* fbi    = (const float*)d_in[6];
    const float* fe1_w  = (const float*)d_in[7];
    const float* fe1_b  = (const float*)d_in[8];
    const float* feln1g = (const float*)d_in[9];
    const float* feln1b = (const float*)d_in[10];
    const float* fe2_w  = (const float*)d_in[11];
    const float* fe2_b  = (const float*)d_in[12];
    const float* feln2g = (const float*)d_in[13];
    const float* feln2b = (const float*)d_in[14];
    const float* in_w   = (const float*)d_in[15];
    const float* in_b   = (const float*)d_in[16];
    const float* ao_w   = (const float*)d_in[17];
    const float* ao_b   = (const float*)d_in[18];
    const float* n1_g   = (const float*)d_in[19];
    const float* n1_b   = (const float*)d_in[20];
    const float* f1_w   = (const float*)d_in[21];
    const float* f1_b   = (const float*)d_in[22];
    const float* f2_w   = (const float*)d_in[23];
    const float* f2_b   = (const float*)d_in[24];
    const float* n2_g   = (const float*)d_in[25];
    const float* n2_b   = (const float*)d_in[26];
    const float* op_w   = (const float*)d_in[27];
    const float* op_b   = (const float*)d_in[28];
    float* out = (float*)d_out;

    unsigned *p_peh, *p_pel, *p_feath, *p_featl, *p_spath, *p_spatl;
    unsigned *p_h1h, *p_h1l, *p_freqh, *p_freql, *p_qkh, *p_qkl;
    unsigned *p_oh, *p_ol, *p_xh, *p_xl, *p_ffhh, *p_ffhl, *p_x2h, *p_x2l;
    unsigned *p_wh, *p_wl;
    float *p_spatial, *p_v, *p_x;
    cudaGetSymbolAddress((void**)&p_peh, g_peh);
    cudaGetSymbolAddress((void**)&p_pel, g_pel);
    cudaGetSymbolAddress((void**)&p_feath, g_feath);
    cudaGetSymbolAddress((void**)&p_featl, g_featl);
    cudaGetSymbolAddress((void**)&p_spatial, g_spatial);
    cudaGetSymbolAddress((void**)&p_spath, g_spath);
    cudaGetSymbolAddress((void**)&p_spatl, g_spatl);
    cudaGetSymbolAddress((void**)&p_h1h, g_h1h);
    cudaGetSymbolAddress((void**)&p_h1l, g_h1l);
    cudaGetSymbolAddress((void**)&p_freqh, g_freqh);
    cudaGetSymbolAddress((void**)&p_freql, g_freql);
    cudaGetSymbolAddress((void**)&p_qkh, g_qkh);
    cudaGetSymbolAddress((void**)&p_qkl, g_qkl);
    cudaGetSymbolAddress((void**)&p_v, g_v);
    cudaGetSymbolAddress((void**)&p_oh, g_oh);
    cudaGetSymbolAddress((void**)&p_ol, g_ol);
    cudaGetSymbolAddress((void**)&p_x, g_x);
    cudaGetSymbolAddress((void**)&p_xh, g_xh);
    cudaGetSymbolAddress((void**)&p_xl, g_xl);
    cudaGetSymbolAddress((void**)&p_ffhh, g_ffhh);
    cudaGetSymbolAddress((void**)&p_ffhl, g_ffhl);
    cudaGetSymbolAddress((void**)&p_x2h, g_x2h);
    cudaGetSymbolAddress((void**)&p_x2l, g_x2l);
    cudaGetSymbolAddress((void**)&p_wh, g_wh);
    cudaGetSymbolAddress((void**)&p_wl, g_wl);

    // 1) FFT features + PE + weight packing, one launch
    prep_kernel<<<6144 + 1349, 256>>>(image, coords, fbi, p_feath, p_featl,
        p_peh, p_pel, pe_w, fe1_w, fe2_w, in_w, ao_w, f1_w, f2_w, op_w,
        p_wh, p_wl);
    // 2) spatial = PE @ pe_w^T + bias + temb  -> fp32 + packed
    gemm_p<2><<<dim3(4, 64, 1), 128>>>(p_peh, p_pel, p_wh + OFF_PE, p_wl + OFF_PE,
        pe_b, p_spatial, p_spath, p_spatl, 128, 256, 128, labels, temb,
        nullptr, nullptr);
    // 3) freq MLP (packed GEMM+LN)
    gemm_pln<128, false, true><<<128, 128>>>(p_feath, p_featl,
        p_wh + OFF_FE1, p_wl + OFF_FE1, fe1_b, nullptr, feln1g, feln1b,
        nullptr, p_h1h, p_h1l, 8);
    gemm_pln<256, false, false><<<128, 128>>>(p_h1h, p_h1l,
        p_wh + OFF_FE2, p_wl + OFF_FE2, fe2_b, nullptr, feln2g, feln2b,
        nullptr, p_freqh, p_freql, 64);
    // 4) QKV: z=0,1 -> packed qk; z=2 -> fp32 V
    gemm_p<4><<<dim3(4, 64, 3), 128>>>(p_spath, p_spatl,
        p_wh + OFF_IN, p_wl + OFF_IN, in_b, p_v, p_qkh, p_qkl,
        128, 256, 128, nullptr, nullptr, p_freqh, p_freql);
    // 5) fused attention -> packed O
    attn_fused<<<dim3(8, 4, 8), 128>>>(p_qkh, p_qkl, p_v, p_oh, p_ol);
    // 6) ao + residual + LN -> x fp32 + packed
    gemm_pln<256, true, false><<<128, 128>>>(p_oh, p_ol,
        p_wh + OFF_AO, p_wl + OFF_AO, ao_b, p_spatial, n1_g, n1_b,
        p_x, p_xh, p_xl, 128);
    // 7) FFN up (gelu) -> packed
    gemm_p<1><<<dim3(8, 64, 1), 128>>>(p_xh, p_xl, p_wh + OFF_F1, p_wl + OFF_F1,
        f1_b, nullptr, p_ffhh, p_ffhl, 128, 512, 256, nullptr, nullptr,
        nullptr, nullptr);
    // 8) FFN down + residual + LN -> packed
    gemm_pln<256, true, false><<<128, 128>>>(p_ffhh, p_ffhl,
        p_wh + OFF_F2, p_wl + OFF_F2, f2_b, p_x, n2_g, n2_b,
        nullptr, p_x2h, p_x2l, 256);
    // 9) output projection -> fp32 out
    gemm_p<0><<<dim3(4, 64, 1), 128>>>(p_x2h, p_x2l, p_wh + OFF_OP, p_wl + OFF_OP,
        op_b, out, nullptr, nullptr, 128, 256, 128, nullptr, nullptr,
        nullptr, nullptr);
}